// round 1
// baseline (speedup 1.0000x reference)
#include <cuda_runtime.h>
#include <stdint.h>
#include <math.h>

#define NMAX   2048
#define NW     64          // NMAX/32 words per bitset row
#define K      128         // MAX_EGO
#define FNUM   16          // filters
#define M      8           // nodes per filter
#define LAB    16          // label categories
#define LEVELS 4           // WL levels

// ---------------- device scratch (no allocations allowed) ----------------
__device__ uint32_t g_abits[NMAX * NW];           // global adjacency bitset
__device__ uint32_t g_hf[LEVELS * FNUM * M];      // filter WL hashes per level
__device__ uint32_t g_fm[FNUM * M];               // filter node mask (0/1)
__device__ float    g_selff[FNUM];                // per-filter self kernel total

__device__ __forceinline__ uint32_t mixh(uint32_t h) {
    h ^= h >> 16; h *= 0x7FEB352Du;
    h ^= h >> 15; h *= 0x846CA68Bu;
    h ^= h >> 16;
    return h;
}

// ---------------- K0: zero adjacency bitset ----------------
__global__ void k_zero(int words) {
    int i = blockIdx.x * blockDim.x + threadIdx.x;
    if (i < words) g_abits[i] = 0u;
}

// ---------------- K1: scatter edges (both directions) ----------------
__global__ void k_edges(const int* __restrict__ ei, int E2) {
    int e = blockIdx.x * blockDim.x + threadIdx.x;
    if (e >= E2) return;
    int s = ei[e];
    int d = ei[E2 + e];
    atomicOr(&g_abits[s * NW + (d >> 5)], 1u << (d & 31));
    atomicOr(&g_abits[d * NW + (s >> 5)], 1u << (s & 31));
}

// ---------------- K2: filter graphs (CC mask, WL hashes, self_f) ----------------
__global__ void k_filters(const float* __restrict__ A, const float* __restrict__ X) {
    int f = threadIdx.x;
    if (f >= FNUM) return;

    // adjacency bits of filter graph f
    uint32_t adj[M];
    for (int m = 0; m < M; m++) {
        uint32_t r = 0;
        for (int j = 0; j < M; j++)
            if (A[(f * M + m) * M + j] > 0.f) r |= 1u << j;
        adj[m] = r;
    }
    // min-label propagation (exactly M iterations, synchronous update)
    int lbl[M];
    for (int m = 0; m < M; m++) lbl[m] = m;
    for (int it = 0; it < M; it++) {
        int nl[M];
        for (int m = 0; m < M; m++) {
            int mn = M;
            uint32_t r = adj[m];
            while (r) { int j = __ffs(r) - 1; r &= r - 1; mn = min(mn, lbl[j]); }
            nl[m] = min(lbl[m], mn);
        }
        for (int m = 0; m < M; m++) lbl[m] = nl[m];
    }
    int cnt[M];
    for (int m = 0; m < M; m++) {
        int c = 0;
        for (int j = 0; j < M; j++) c += (lbl[j] == lbl[m]);
        cnt[m] = c;
    }
    int best = 0;
    for (int m = 1; m < M; m++) if (cnt[m] > cnt[best]) best = m;  // first max
    uint32_t maskbits = 0;
    for (int m = 0; m < M; m++) if (lbl[m] == lbl[best]) maskbits |= 1u << m;

    // masked adjacency for WL
    uint32_t adjm[M];
    for (int m = 0; m < M; m++)
        adjm[m] = ((maskbits >> m) & 1u) ? (adj[m] & maskbits) : 0u;

    // initial labels = argmax over X (first max)
    uint32_t h[M];
    for (int m = 0; m < M; m++) {
        const float* xr = X + (f * M + m) * LAB;
        int lab = 0; float bv = xr[0];
        for (int l = 1; l < LAB; l++) { float v = xr[l]; if (v > bv) { bv = v; lab = l; } }
        h[m] = mixh((uint32_t)lab + 1u);
    }

    int selff = 0;
    for (int t = 0; t < LEVELS; t++) {
        if (t > 0) {
            uint32_t mh[M], nh[M];
            for (int m = 0; m < M; m++) mh[m] = mixh(h[m]);
            for (int m = 0; m < M; m++) {
                uint32_t msg = 0, r = adjm[m];
                while (r) { int j = __ffs(r) - 1; r &= r - 1; msg += mh[j]; }
                nh[m] = mixh(h[m] * 0x9E3779B1u + msg);
            }
            for (int m = 0; m < M; m++) h[m] = nh[m];
        }
        for (int m = 0; m < M; m++) g_hf[(t * FNUM + f) * M + m] = h[m];
        for (int m = 0; m < M; m++)
            if ((maskbits >> m) & 1u)
                for (int j = 0; j < M; j++)
                    if (((maskbits >> j) & 1u) && h[m] == h[j]) selff++;
    }
    g_selff[f] = (float)selff;
    for (int m = 0; m < M; m++) g_fm[f * M + m] = (maskbits >> m) & 1u;
}

// ---------------- K3: main per-seed kernel ----------------
__global__ void __launch_bounds__(128) k_main(const float* __restrict__ x,
                                              float* __restrict__ out) {
    const int u   = blockIdx.x;
    const int tid = threadIdx.x;
    const int lane = tid & 31;

    __shared__ uint32_t cur[NW], nxt[NW];
    __shared__ int      members[K];
    __shared__ int      pref[NW];
    __shared__ int      s_cnt;
    __shared__ uint32_t sh[K], smh[K];
    __shared__ uint32_t s_hf[LEVELS][FNUM * M];
    __shared__ uint32_t s_fm[FNUM * M];
    __shared__ float    s_selff[FNUM];
    __shared__ int      s_cross[FNUM];
    __shared__ int      s_selfe;

    if (tid < NW) cur[tid] = (tid == (u >> 5)) ? (1u << (u & 31)) : 0u;
    if (tid < FNUM * M) {
        s_fm[tid] = g_fm[tid];
        #pragma unroll
        for (int t = 0; t < LEVELS; t++) s_hf[t][tid] = g_hf[t * FNUM * M + tid];
    }
    if (tid < FNUM) { s_selff[tid] = g_selff[tid]; s_cross[tid] = 0; }
    if (tid == 0) s_selfe = 0;
    __syncthreads();

    // ---- 3-hop BFS over the global bitset ----
    for (int hop = 0; hop < 3; hop++) {
        if (tid < NW) nxt[tid] = cur[tid];
        __syncthreads();
        #pragma unroll
        for (int k = 0; k < 16; k++) {
            int v = tid * 16 + k;
            if ((cur[v >> 5] >> (v & 31)) & 1u) {
                const uint32_t* row = &g_abits[v * NW];
                #pragma unroll 8
                for (int w = 0; w < NW; w++) {
                    uint32_t r = row[w];
                    if (r) atomicOr(&nxt[w], r);
                }
            }
        }
        __syncthreads();
        if (tid < NW) cur[tid] = nxt[tid];
        __syncthreads();
    }

    // ---- enumerate members: seed first, then ascending index, truncate at K ----
    if (tid < NW) {
        uint32_t wv = cur[tid];
        if (tid == (u >> 5)) wv &= ~(1u << (u & 31));
        nxt[tid] = wv;  // seedless bits
    }
    __syncthreads();
    if (tid == 0) {
        int acc = 0;
        for (int w = 0; w < NW; w++) { pref[w] = acc; acc += __popc(nxt[w]); }
        s_cnt = min(acc + 1, K);
        members[0] = u;
    }
    __syncthreads();
    if (tid < NW) {
        uint32_t wv = nxt[tid];
        int base = 1 + pref[tid];
        while (wv && base < K) {
            int b = __ffs(wv) - 1; wv &= wv - 1;
            members[base++] = (tid << 5) + b;
        }
    }
    __syncthreads();
    const int cnt = s_cnt;

    // ---- local adjacency (128-bit row in registers) + initial hash ----
    uint32_t row[4] = {0u, 0u, 0u, 0u};
    if (tid < cnt) {
        int g = members[tid];
        const uint32_t* arow = &g_abits[g * NW];
        for (int j = 0; j < cnt; j++) {
            int mj = members[j];
            uint32_t bit = (arow[mj >> 5] >> (mj & 31)) & 1u;
            row[j >> 5] |= bit << (j & 31);
        }
        const float* xr = x + g * LAB;
        int lab = 0; float bv = xr[0];
        #pragma unroll
        for (int l = 1; l < LAB; l++) { float v = xr[l]; if (v > bv) { bv = v; lab = l; } }
        sh[tid] = mixh((uint32_t)lab + 1u);
    }
    __syncthreads();

    // ---- WL levels ----
    for (int t = 0; t < LEVELS; t++) {
        if (t > 0) {
            if (tid < cnt) smh[tid] = mixh(sh[tid]);
            __syncthreads();
            uint32_t nh = 0;
            if (tid < cnt) {
                uint32_t msg = 0;
                #pragma unroll
                for (int w = 0; w < 4; w++) {
                    uint32_t r = row[w];
                    while (r) { int b = __ffs(r) - 1; r &= r - 1; msg += smh[(w << 5) + b]; }
                }
                nh = mixh(sh[tid] * 0x9E3779B1u + msg);
            }
            __syncthreads();
            if (tid < cnt) sh[tid] = nh;
            __syncthreads();
        }

        const bool valid = tid < cnt;
        const uint32_t hi = valid ? sh[tid] : 0u;

        // self_e: pairs with equal hash among valid members
        unsigned se = 0;
        if (valid) {
            for (int j = 0; j < cnt; j++) se += (sh[j] == hi);
        }
        se = __reduce_add_sync(0xffffffffu, se);
        if (lane == 0 && se) atomicAdd(&s_selfe, (int)se);

        // cross: matches against masked filter-node hashes
        #pragma unroll
        for (int f = 0; f < FNUM; f++) {
            unsigned cc = 0;
            if (valid) {
                #pragma unroll
                for (int m = 0; m < M; m++)
                    cc += (unsigned)((hi == s_hf[t][f * M + m]) & (s_fm[f * M + m] != 0u));
            }
            cc = __reduce_add_sync(0xffffffffu, cc);
            if (lane == 0 && cc) atomicAdd(&s_cross[f], (int)cc);
        }
        __syncthreads();
    }

    if (tid < FNUM) {
        float denom = sqrtf((float)s_selfe * s_selff[tid]);
        float v = (float)s_cross[tid] / denom;
        if (!isfinite(v)) v = 0.f;
        out[u * FNUM + tid] = v;
    }
}

// ---------------- launch ----------------
extern "C" void kernel_launch(void* const* d_in, const int* in_sizes, int n_in,
                              void* d_out, int out_size) {
    const float* x  = (const float*)d_in[0];
    const int*   ei = (const int*)d_in[1];
    const float* A  = (const float*)d_in[3];
    const float* X  = (const float*)d_in[4];
    float* out = (float*)d_out;

    const int N  = in_sizes[0] / LAB;    // 2048
    const int E2 = in_sizes[1] / 2;      // 8192 directed edges

    const int words = N * NW;
    k_zero<<<(words + 255) / 256, 256>>>(words);
    k_edges<<<(E2 + 255) / 256, 256>>>(ei, E2);
    k_filters<<<1, 32>>>(A, X);
    k_main<<<N, 128>>>(x, out);
}